// round 13
// baseline (speedup 1.0000x reference)
#include <cuda_runtime.h>
#include <cstdint>

// VoConstruction: out = Re( O @ (Umat d Umat^H) ), algebraically reduced.
//   delta = U[:,2] cancels exactly; only cos(2psi) survives the Re() cast.
//   H00 = (l1+l2) + (l1-l2)cos2t, H11 = (l1+l2) - (l1-l2)cos2t,
//   hr  = (l2-l1) sin2t cos2psi;  out = O_real * [[H00,hr],[hr,H11]]
//
// R13 (= R12 resubmit after infra failure): sm_100 256-bit vector memory ops.
// 8 consecutive elems/thread: 3x LDG.256 (U), 1x each x1/x2, 4x STG.256.
// 32B/lane contiguous -> 1 L1 wavefront per 128B line; ~2x fewer memory
// instructions per byte than R11. MUFU sincos(theta) + MUFU cos(psi).

__device__ __forceinline__ void ldg256(const float* p, float* r) {
    asm volatile("ld.global.nc.v8.b32 {%0,%1,%2,%3,%4,%5,%6,%7}, [%8];"
                 : "=f"(r[0]), "=f"(r[1]), "=f"(r[2]), "=f"(r[3]),
                   "=f"(r[4]), "=f"(r[5]), "=f"(r[6]), "=f"(r[7])
                 : "l"(p));
}

__device__ __forceinline__ void stg256(float* p, const float* r) {
    asm volatile("st.global.v8.b32 [%0], {%1,%2,%3,%4,%5,%6,%7,%8};"
                 :: "l"(p),
                    "f"(r[0]), "f"(r[1]), "f"(r[2]), "f"(r[3]),
                    "f"(r[4]), "f"(r[5]), "f"(r[6]), "f"(r[7])
                 : "memory");
}

__global__ __launch_bounds__(256)
void vo_kernel8(const float* __restrict__ U,
                const float* __restrict__ x1,
                const float* __restrict__ x2,
                const float* __restrict__ O4,
                float* __restrict__ out,   // [B,4] f32
                int nv)                     // nv = n/8
{
    int t = blockIdx.x * blockDim.x + threadIdx.x;
    if (t >= nv) return;

    const float* up = U + 24l * t;
    float u[24], a[8], c[8];
    // 5 front-batched 1024B/warp loads
    ldg256(up +  0, u +  0);
    ldg256(up +  8, u +  8);
    ldg256(up + 16, u + 16);
    ldg256(x1 + 8l * t, a);
    ldg256(x2 + 8l * t, c);

    float o00 = O4[0], o01 = O4[1], o10 = O4[2], o11 = O4[3];

    float* op = out + 32l * t;
    #pragma unroll
    for (int p = 0; p < 4; p++) {          // 4 store-pairs
        float res[8];
        #pragma unroll
        for (int e = 0; e < 2; e++) {      // 2 elems per pair
            int k = 2 * p + e;
            float psi   = u[3 * k + 0];
            float theta = u[3 * k + 1];
            float l1 = a[k];
            float l2 = c[k] * (1.0f - fabsf(l1));

            float s2t, c2t;
            __sincosf(2.0f * theta, &s2t, &c2t);
            float c2p = __cosf(2.0f * psi);

            float sum = l1 + l2, dif = l1 - l2;
            float H00 = fmaf(dif,  c2t, sum);
            float H11 = fmaf(-dif, c2t, sum);
            float hr  = (-dif * s2t) * c2p;

            res[4 * e + 0] = fmaf(o00, H00, o01 * hr);
            res[4 * e + 1] = fmaf(o00, hr,  o01 * H11);
            res[4 * e + 2] = fmaf(o10, H00, o11 * hr);
            res[4 * e + 3] = fmaf(o10, hr,  o11 * H11);
        }
        stg256(op + 8 * p, res);
    }
}

// Scalar tail for n % 8 != 0 (unused when B is a multiple of 8).
__global__ __launch_bounds__(256)
void vo_tail(const float* __restrict__ U,
             const float* __restrict__ x1,
             const float* __restrict__ x2,
             const float* __restrict__ O4,
             float4* __restrict__ out,
             int start, int n)
{
    int b = start + blockIdx.x * blockDim.x + threadIdx.x;
    if (b >= n) return;
    float psi = U[3 * b], theta = U[3 * b + 1];
    float l1 = x1[b];
    float l2 = x2[b] * (1.0f - fabsf(l1));
    float s2t, c2t;
    __sincosf(2.0f * theta, &s2t, &c2t);
    float c2p = __cosf(2.0f * psi);
    float sum = l1 + l2, dif = l1 - l2;
    float H00 = fmaf(dif,  c2t, sum);
    float H11 = fmaf(-dif, c2t, sum);
    float hr  = (-dif * s2t) * c2p;
    float o00 = O4[0], o01 = O4[1], o10 = O4[2], o11 = O4[3];
    out[b] = make_float4(fmaf(o00, H00, o01 * hr),
                         fmaf(o00, hr,  o01 * H11),
                         fmaf(o10, H00, o11 * hr),
                         fmaf(o10, hr,  o11 * H11));
}

extern "C" void kernel_launch(void* const* d_in, const int* in_sizes, int n_in,
                              void* d_out, int out_size)
{
    const float* U  = (const float*)d_in[0];   // [B,3] f32
    const float* x1 = (const float*)d_in[1];   // [B]   f32
    const float* x2 = (const float*)d_in[2];   // [B]   f32
    const float* O4 = (const float*)d_in[3];   // [4]   f32 (real part of O)

    long n = in_sizes[0] / 3;
    long n_out = (long)out_size / 4;
    if (n_out < n) n = n_out;
    if (n <= 0) return;

    long nv = n / 8;
    int threads = 256;
    if (nv > 0) {
        int blocks = (int)((nv + threads - 1) / threads);
        vo_kernel8<<<blocks, threads>>>(U, x1, x2, O4, (float*)d_out, (int)nv);
    }
    if (n - nv * 8 > 0) {
        vo_tail<<<1, 256>>>(U, x1, x2, O4, (float4*)d_out, (int)(nv * 8), (int)n);
    }
}

// round 14
// speedup vs baseline: 1.2232x; 1.2232x over previous
#include <cuda_runtime.h>

// VoConstruction: out = Re( O @ (Umat d Umat^H) ), algebraically reduced.
//   delta = U[:,2] cancels exactly; sin(2psi) dead under the Re() cast.
//   H00 = (l1+l2) + (l1-l2)cos2t, H11 = (l1+l2) - (l1-l2)cos2t,
//   hr  = (l2-l1) sin2t cos2psi;  out = O_real * [[H00,hr],[hr,H11]]
//
// R14: persistent grid-stride version of R11. Scalar one-elem-per-lane
// coalesced accesses (proven optimal: wide vectors double L1 wavefront cost
// via within-instruction replays — R6/R13 both regressed). 4-way split-grid
// per iteration (16 front-batched independent loads), exactly one wave of
// CTAs -> no wave-quantization tail.

__global__ __launch_bounds__(256)
void vo_persist(const float* __restrict__ U,
                const float* __restrict__ x1,
                const float* __restrict__ x2,
                const float* __restrict__ O4,
                float4* __restrict__ out,   // [B] float4 = [B,2,2] f32
                int n, int q)               // q = ceil(n/4)
{
    int stride = gridDim.x * blockDim.x;
    float o00 = O4[0], o01 = O4[1], o10 = O4[2], o11 = O4[3];

    for (int i = blockIdx.x * blockDim.x + threadIdx.x; i < q; i += stride) {
        int b[4];
        bool live[4];
        #pragma unroll
        for (int k = 0; k < 4; k++) {
            int bb = i + k * q;
            live[k] = (bb < n);
            b[k] = live[k] ? bb : i;   // clamp loads; stores predicated
        }

        // Front-batched independent loads (16 LDGs, coalesced per quarter)
        float psi[4], the[4], l1v[4], x2v[4];
        #pragma unroll
        for (int k = 0; k < 4; k++) {
            psi[k] = __ldg(&U[3 * b[k] + 0]);
            the[k] = __ldg(&U[3 * b[k] + 1]);
        }
        #pragma unroll
        for (int k = 0; k < 4; k++) l1v[k] = __ldg(&x1[b[k]]);
        #pragma unroll
        for (int k = 0; k < 4; k++) x2v[k] = __ldg(&x2[b[k]]);

        #pragma unroll
        for (int k = 0; k < 4; k++) {
            float l1 = l1v[k];
            float l2 = x2v[k] * (1.0f - fabsf(l1));

            float s2t, c2t;
            __sincosf(2.0f * the[k], &s2t, &c2t);
            float c2p = __cosf(2.0f * psi[k]);

            float sum = l1 + l2, dif = l1 - l2;
            float H00 = fmaf(dif,  c2t, sum);
            float H11 = fmaf(-dif, c2t, sum);
            float hr  = (-dif * s2t) * c2p;

            if (live[k]) {
                float4 r = make_float4(fmaf(o00, H00, o01 * hr),
                                       fmaf(o00, hr,  o01 * H11),
                                       fmaf(o10, H00, o11 * hr),
                                       fmaf(o10, hr,  o11 * H11));
                __stcs(&out[b[k]], r);   // write-once: evict-first
            }
        }
    }
}

extern "C" void kernel_launch(void* const* d_in, const int* in_sizes, int n_in,
                              void* d_out, int out_size)
{
    const float* U  = (const float*)d_in[0];   // [B,3] f32
    const float* x1 = (const float*)d_in[1];   // [B]   f32
    const float* x2 = (const float*)d_in[2];   // [B]   f32
    const float* O4 = (const float*)d_in[3];   // [4]   f32 (real part of O)

    long n = in_sizes[0] / 3;
    long n_out = (long)out_size / 4;
    if (n_out < n) n = n_out;
    if (n <= 0) return;

    long q = (n + 3) / 4;
    int threads = 256;

    // Exactly one resident wave: SMs * max co-resident CTAs of this kernel.
    static int blocks_cached = 0;
    if (blocks_cached == 0) {
        int dev = 0, sms = 148, per_sm = 8;
        cudaGetDevice(&dev);
        cudaDeviceGetAttribute(&sms, cudaDevAttrMultiProcessorCount, dev);
        cudaOccupancyMaxActiveBlocksPerMultiprocessor(&per_sm, vo_persist,
                                                      threads, 0);
        if (per_sm < 1) per_sm = 1;
        blocks_cached = sms * per_sm;
    }
    int blocks = blocks_cached;
    long max_blocks = (q + threads - 1) / threads;
    if (blocks > max_blocks) blocks = (int)max_blocks;

    vo_persist<<<blocks, threads>>>(U, x1, x2, O4, (float4*)d_out,
                                    (int)n, (int)q);
}

// round 16
// speedup vs baseline: 1.2320x; 1.0072x over previous
#include <cuda_runtime.h>

// VoConstruction: out = Re( O @ (Umat d Umat^H) ), algebraically reduced.
//   A=diag(e^{ip},e^{-ip}), B=rot(t), C=diag(e^{id},e^{-id}):
//   C d C^H = d exactly -> delta = U[:,2] never loaded.
//   H00 = (l1+l2) + (l1-l2)cos2t, H11 = (l1+l2) - (l1-l2)cos2t,
//   hr  = (l2-l1) sin2t cos2psi   (sin2psi dead under the float32/Re cast)
//   out = O_real * [[H00, hr], [hr, H11]]
//
// R16 (= R15 resubmit after infra failure): champion R11 structure —
// 4 elems/thread via 4-way grid split, scalar one-elem-per-lane coalesced
// loads (wide vectors regress: 2x L1 wavefront replay cost), 16 front-batched
// __ldg, MUFU sincos/cos, __stcs streaming stores. Dead-sin and dead-policy
// code removed.

__global__ __launch_bounds__(256)
void vo_final(const float* __restrict__ U,
              const float* __restrict__ x1,
              const float* __restrict__ x2,
              const float* __restrict__ O4,
              float4* __restrict__ out,   // [B] float4 = [B,2,2] f32
              int n, int q)               // q = ceil(n/4)
{
    int i = blockIdx.x * blockDim.x + threadIdx.x;
    if (i >= q) return;

    int b[4];
    bool live[4];
    #pragma unroll
    for (int k = 0; k < 4; k++) {
        int bb = i + k * q;
        live[k] = (bb < n);
        b[k] = live[k] ? bb : i;   // clamp loads in-bounds; stores predicated
    }

    // Front-batched independent loads (16 LDGs, coalesced within each quarter)
    float psi[4], the[4], l1v[4], x2v[4];
    #pragma unroll
    for (int k = 0; k < 4; k++) {
        psi[k] = __ldg(&U[3 * b[k] + 0]);
        the[k] = __ldg(&U[3 * b[k] + 1]);
    }
    #pragma unroll
    for (int k = 0; k < 4; k++) l1v[k] = __ldg(&x1[b[k]]);
    #pragma unroll
    for (int k = 0; k < 4; k++) x2v[k] = __ldg(&x2[b[k]]);

    float o00 = O4[0], o01 = O4[1], o10 = O4[2], o11 = O4[3];

    #pragma unroll
    for (int k = 0; k < 4; k++) {
        float l1 = l1v[k];
        float l2 = x2v[k] * (1.0f - fabsf(l1));

        float s2t, c2t;
        __sincosf(2.0f * the[k], &s2t, &c2t);
        float c2p = __cosf(2.0f * psi[k]);

        float sum = l1 + l2, dif = l1 - l2;
        float H00 = fmaf(dif,  c2t, sum);
        float H11 = fmaf(-dif, c2t, sum);
        float hr  = (-dif * s2t) * c2p;

        if (live[k]) {
            float4 r = make_float4(fmaf(o00, H00, o01 * hr),
                                   fmaf(o00, hr,  o01 * H11),
                                   fmaf(o10, H00, o11 * hr),
                                   fmaf(o10, hr,  o11 * H11));
            __stcs(&out[b[k]], r);   // write-once stream: evict-first
        }
    }
}

extern "C" void kernel_launch(void* const* d_in, const int* in_sizes, int n_in,
                              void* d_out, int out_size)
{
    const float* U  = (const float*)d_in[0];   // [B,3] f32
    const float* x1 = (const float*)d_in[1];   // [B]   f32
    const float* x2 = (const float*)d_in[2];   // [B]   f32
    const float* O4 = (const float*)d_in[3];   // [4]   f32 (real part of O)

    long n = in_sizes[0] / 3;
    long n_out = (long)out_size / 4;
    if (n_out < n) n = n_out;
    if (n <= 0) return;

    long q = (n + 3) / 4;
    int threads = 256;
    int blocks = (int)((q + threads - 1) / threads);
    vo_final<<<blocks, threads>>>(U, x1, x2, O4, (float4*)d_out,
                                  (int)n, (int)q);
}

// round 17
// speedup vs baseline: 1.2409x; 1.0073x over previous
#include <cuda_runtime.h>

// VoConstruction: out = Re( O @ (Umat d Umat^H) ), algebraically reduced.
//   A=diag(e^{ip},e^{-ip}), B=rot(t), C=diag(e^{id},e^{-id}):
//   C d C^H = d exactly -> delta = U[:,2] never loaded.
//   H00 = (l1+l2) + (l1-l2)cos2t, H11 = (l1+l2) - (l1-l2)cos2t,
//   hr  = (l2-l1) sin2t cos2psi   (sin2psi dead under the float32/Re cast)
//   out = O_real * [[H00, hr], [hr, H11]]
//
// R17 (final): champion structure — 4 elems/thread via 4-way grid split,
// scalar one-elem-per-lane coalesced loads (wide vectors proven to regress:
// 2x L1 wavefront replay cost), 16 front-batched __ldg, MUFU sincos/cos,
// __stcs streaming stores — plus a specialized no-predication kernel for
// n % 4 == 0 (always true for this dataset's B).

__device__ __forceinline__ float4 vo_elem(float psi, float theta,
                                          float l1, float xx2,
                                          float o00, float o01,
                                          float o10, float o11)
{
    float l2 = xx2 * (1.0f - fabsf(l1));
    float s2t, c2t;
    __sincosf(2.0f * theta, &s2t, &c2t);
    float c2p = __cosf(2.0f * psi);
    float sum = l1 + l2, dif = l1 - l2;
    float H00 = fmaf(dif,  c2t, sum);
    float H11 = fmaf(-dif, c2t, sum);
    float hr  = (-dif * s2t) * c2p;
    return make_float4(fmaf(o00, H00, o01 * hr),
                       fmaf(o00, hr,  o01 * H11),
                       fmaf(o10, H00, o11 * hr),
                       fmaf(o10, hr,  o11 * H11));
}

// Fast path: n == 4*q exactly (no bounds predication anywhere).
__global__ __launch_bounds__(256)
void vo_final_div4(const float* __restrict__ U,
                   const float* __restrict__ x1,
                   const float* __restrict__ x2,
                   const float* __restrict__ O4,
                   float4* __restrict__ out,   // [B] float4 = [B,2,2] f32
                   int q)                      // q = n/4
{
    int i = blockIdx.x * blockDim.x + threadIdx.x;
    if (i >= q) return;

    int b0 = i, b1 = i + q, b2 = i + 2 * q, b3 = i + 3 * q;

    // Front-batched independent loads (16 LDGs, coalesced within each quarter)
    float p0 = __ldg(&U[3 * b0 + 0]), t0 = __ldg(&U[3 * b0 + 1]);
    float p1 = __ldg(&U[3 * b1 + 0]), t1 = __ldg(&U[3 * b1 + 1]);
    float p2 = __ldg(&U[3 * b2 + 0]), t2 = __ldg(&U[3 * b2 + 1]);
    float p3 = __ldg(&U[3 * b3 + 0]), t3 = __ldg(&U[3 * b3 + 1]);
    float a0 = __ldg(&x1[b0]), a1 = __ldg(&x1[b1]);
    float a2 = __ldg(&x1[b2]), a3 = __ldg(&x1[b3]);
    float c0 = __ldg(&x2[b0]), c1 = __ldg(&x2[b1]);
    float c2 = __ldg(&x2[b2]), c3 = __ldg(&x2[b3]);

    float o00 = O4[0], o01 = O4[1], o10 = O4[2], o11 = O4[3];

    __stcs(&out[b0], vo_elem(p0, t0, a0, c0, o00, o01, o10, o11));
    __stcs(&out[b1], vo_elem(p1, t1, a1, c1, o00, o01, o10, o11));
    __stcs(&out[b2], vo_elem(p2, t2, a2, c2, o00, o01, o10, o11));
    __stcs(&out[b3], vo_elem(p3, t3, a3, c3, o00, o01, o10, o11));
}

// Generic path (any n): clamp loads, predicate stores.
__global__ __launch_bounds__(256)
void vo_final_gen(const float* __restrict__ U,
                  const float* __restrict__ x1,
                  const float* __restrict__ x2,
                  const float* __restrict__ O4,
                  float4* __restrict__ out,
                  int n, int q)               // q = ceil(n/4)
{
    int i = blockIdx.x * blockDim.x + threadIdx.x;
    if (i >= q) return;

    int b[4];
    bool live[4];
    #pragma unroll
    for (int k = 0; k < 4; k++) {
        int bb = i + k * q;
        live[k] = (bb < n);
        b[k] = live[k] ? bb : i;
    }

    float psi[4], the[4], l1v[4], x2v[4];
    #pragma unroll
    for (int k = 0; k < 4; k++) {
        psi[k] = __ldg(&U[3 * b[k] + 0]);
        the[k] = __ldg(&U[3 * b[k] + 1]);
    }
    #pragma unroll
    for (int k = 0; k < 4; k++) l1v[k] = __ldg(&x1[b[k]]);
    #pragma unroll
    for (int k = 0; k < 4; k++) x2v[k] = __ldg(&x2[b[k]]);

    float o00 = O4[0], o01 = O4[1], o10 = O4[2], o11 = O4[3];

    #pragma unroll
    for (int k = 0; k < 4; k++) {
        if (live[k])
            __stcs(&out[b[k]], vo_elem(psi[k], the[k], l1v[k], x2v[k],
                                       o00, o01, o10, o11));
    }
}

extern "C" void kernel_launch(void* const* d_in, const int* in_sizes, int n_in,
                              void* d_out, int out_size)
{
    const float* U  = (const float*)d_in[0];   // [B,3] f32
    const float* x1 = (const float*)d_in[1];   // [B]   f32
    const float* x2 = (const float*)d_in[2];   // [B]   f32
    const float* O4 = (const float*)d_in[3];   // [4]   f32 (real part of O)

    long n = in_sizes[0] / 3;
    long n_out = (long)out_size / 4;
    if (n_out < n) n = n_out;
    if (n <= 0) return;

    int threads = 256;
    if ((n & 3) == 0) {
        long q = n / 4;
        int blocks = (int)((q + threads - 1) / threads);
        vo_final_div4<<<blocks, threads>>>(U, x1, x2, O4,
                                           (float4*)d_out, (int)q);
    } else {
        long q = (n + 3) / 4;
        int blocks = (int)((q + threads - 1) / threads);
        vo_final_gen<<<blocks, threads>>>(U, x1, x2, O4,
                                          (float4*)d_out, (int)n, (int)q);
    }
}